// round 1
// baseline (speedup 1.0000x reference)
#include <cuda_runtime.h>

#define NEVT    400000
#define NLOCS   100000
#define NTIMES  168
#define NKEYS   (NLOCS * NTIMES)      /* 16,800,000 */
#define OUTC    256
#define SCAN_BS 4096
#define SCAN_T  512
#define NSBLK   ((NKEYS + SCAN_BS - 1) / SCAN_BS)   /* 4102 */

typedef unsigned int u32;
typedef unsigned long long u64;

// ---------------- scratch (static device allocations) ----------------
__device__ u32 g_cnt[NKEYS];          // histogram, then overwritten with row ids
__device__ u64 g_bsums[NSBLK];        // packed (flags<<32 | counts) block sums
__device__ u32 g_numrows;             // K = number of unique (x,t) keys
__device__ u32 g_key[NEVT];           // unique key per row
__device__ u32 g_count[NEVT];         // events per row
__device__ u32 g_cursor[NEVT];        // CSR offset, advanced by scatter pass
__device__ u32 g_evtu[NEVT];          // u index per compacted event slot
__device__ float g_P1[(size_t)NLOCS * OUTC];   // loc_table @ W[0:64]
__device__ float g_P2b[NTIMES * OUTC];         // time_table @ W[64:96] + b
__device__ float g_P3[NTIMES * OUTC];          // user_table @ W[96:160]

// ---------------- helpers ----------------
template <int NT>
__device__ __forceinline__ u64 block_incl_scan(u64 v, u64* sm) {
    int tid = threadIdx.x;
    int lane = tid & 31, wid = tid >> 5;
    u64 x = v;
#pragma unroll
    for (int d = 1; d < 32; d <<= 1) {
        u64 y = __shfl_up_sync(0xffffffffu, x, d);
        if (lane >= d) x += y;
    }
    if (lane == 31) sm[wid] = x;
    __syncthreads();
    if (wid == 0) {
        u64 w = (lane < (NT / 32)) ? sm[lane] : 0ull;
#pragma unroll
        for (int d = 1; d < 32; d <<= 1) {
            u64 y = __shfl_up_sync(0xffffffffu, w, d);
            if (lane >= d) w += y;
        }
        if (lane < (NT / 32)) sm[lane] = w;
    }
    __syncthreads();
    u64 base = wid ? sm[wid - 1] : 0ull;
    u64 r = x + base;
    __syncthreads();   // smem safe for reuse after return
    return r;
}

// ---------------- kernels ----------------
__global__ void k_zero() {
    size_t i = (size_t)blockIdx.x * blockDim.x + threadIdx.x;
    size_t stride = (size_t)gridDim.x * blockDim.x;
    uint4 z = make_uint4(0, 0, 0, 0);
    for (size_t idx = i; idx < NKEYS / 4; idx += stride)
        reinterpret_cast<uint4*>(g_cnt)[idx] = z;
}

__global__ void k_hist(const int* __restrict__ x, const int* __restrict__ t) {
    int j = blockIdx.x * blockDim.x + threadIdx.x;
    if (j < NEVT) {
        u32 key = (u32)x[j] * NTIMES + (u32)t[j];
        atomicAdd(&g_cnt[key], 1u);
    }
}

__global__ void k_s1() {
    int tid = threadIdx.x;
    size_t base = (size_t)blockIdx.x * SCAN_BS;
    u32 fs = 0, cs = 0;
    for (int i = tid; i < SCAN_BS; i += SCAN_T) {
        size_t idx = base + i;
        if (idx < NKEYS) {
            u32 c = g_cnt[idx];
            fs += (c != 0);
            cs += c;
        }
    }
    u64 v = ((u64)fs << 32) | cs;
    __shared__ u64 sm[SCAN_T / 32];
    int lane = tid & 31, wid = tid >> 5;
#pragma unroll
    for (int d = 16; d; d >>= 1) v += __shfl_down_sync(0xffffffffu, v, d);
    if (lane == 0) sm[wid] = v;
    __syncthreads();
    if (tid == 0) {
        u64 s = 0;
        for (int i = 0; i < SCAN_T / 32; i++) s += sm[i];
        g_bsums[blockIdx.x] = s;
    }
}

__global__ void k_s2() {
    __shared__ u64 sm[32];
    __shared__ u64 s_carry;
    __shared__ u64 s_total;
    int tid = threadIdx.x;
    if (tid == 0) s_carry = 0;
    __syncthreads();
    for (int base = 0; base < NSBLK; base += 1024) {
        int i = base + tid;
        u64 v = (i < NSBLK) ? g_bsums[i] : 0ull;
        u64 incl = block_incl_scan<1024>(v, sm);
        if (tid == 1023) s_total = incl;
        __syncthreads();
        u64 carry = s_carry;
        if (i < NSBLK) g_bsums[i] = carry + incl - v;   // exclusive prefix
        __syncthreads();
        if (tid == 0) s_carry = carry + s_total;
        __syncthreads();
    }
    if (tid == 0) g_numrows = (u32)(s_carry >> 32);
}

__global__ void k_s3() {
    __shared__ u32 s_cnt[SCAN_BS];
    __shared__ u64 sm[SCAN_T / 32];
    int tid = threadIdx.x;
    size_t base = (size_t)blockIdx.x * SCAN_BS;
    for (int i = tid; i < SCAN_BS; i += SCAN_T) {
        size_t idx = base + i;
        s_cnt[i] = (idx < NKEYS) ? g_cnt[idx] : 0u;
    }
    __syncthreads();
    u32 fs = 0, cs = 0;
    int e0 = tid * 8;
#pragma unroll
    for (int e = 0; e < 8; e++) {
        u32 c = s_cnt[e0 + e];
        fs += (c != 0);
        cs += c;
    }
    u64 mine = ((u64)fs << 32) | cs;
    u64 incl = block_incl_scan<SCAN_T>(mine, sm);
    u64 excl = incl - mine;
    u64 bbase = g_bsums[blockIdx.x];
    u32 frun = (u32)((excl >> 32) + (bbase >> 32));
    u32 crun = (u32)(excl & 0xffffffffull) + (u32)(bbase & 0xffffffffull);
#pragma unroll
    for (int e = 0; e < 8; e++) {
        size_t idx = base + e0 + e;
        u32 c = s_cnt[e0 + e];
        if (idx < NKEYS && c) {
            g_key[frun] = (u32)idx;
            g_count[frun] = c;
            g_cursor[frun] = crun;   // CSR start (will advance to end)
            g_cnt[idx] = frun;       // overwrite histogram with row id
            frun++;
            crun += c;
        }
    }
}

__global__ void k_scatter(const int* __restrict__ x, const int* __restrict__ t,
                          const int* __restrict__ u) {
    int j = blockIdx.x * blockDim.x + threadIdx.x;
    if (j < NEVT) {
        u32 key = (u32)x[j] * NTIMES + (u32)t[j];
        u32 row = g_cnt[key];
        u32 pos = atomicAdd(&g_cursor[row], 1u);
        g_evtu[pos] = (u32)u[j];
    }
}

// Tiny precomputes: P2b = time_table @ W[64:96] + b ; P3 = user_table @ W[96:160]
__global__ void k_p23(const float* __restrict__ time_table,
                      const float* __restrict__ user_table,
                      const float* __restrict__ W, const float* __restrict__ b) {
    int r = blockIdx.x;
    int c = threadIdx.x;
    float a2 = b[c];
#pragma unroll 8
    for (int k = 0; k < 32; k++)
        a2 += time_table[r * 32 + k] * W[(64 + k) * OUTC + c];
    g_P2b[r * OUTC + c] = a2;
    float a3 = 0.f;
#pragma unroll 8
    for (int k = 0; k < 64; k++)
        a3 += user_table[r * 64 + k] * W[(96 + k) * OUTC + c];
    g_P3[r * OUTC + c] = a3;
}

// P1 = loc_table @ W[0:64]  (100000x64 @ 64x256), register-tiled 4 cols x 8 rows
__global__ void __launch_bounds__(256) k_p1(const float* __restrict__ loc_table,
                                            const float* __restrict__ W) {
    __shared__ float Wsm[32 * 256];   // one 32-row K-chunk of W
    __shared__ float Lsm[32 * 64];    // 32 loc rows
    int tid = threadIdx.x;
    int rowbase = blockIdx.x * 32;
    for (int idx = tid; idx < 32 * 64; idx += 256)
        Lsm[idx] = loc_table[(size_t)rowbase * 64 + idx];
    int col = tid & 63;     // handles cols col, col+64, col+128, col+192
    int rgrp = tid >> 6;    // 0..3 -> rows rgrp*8 .. rgrp*8+7
    float acc[4][8];
#pragma unroll
    for (int a = 0; a < 4; a++)
#pragma unroll
        for (int r = 0; r < 8; r++) acc[a][r] = 0.f;

    for (int kc = 0; kc < 2; kc++) {
        __syncthreads();
        for (int idx = tid; idx < 32 * 256; idx += 256)
            Wsm[idx] = W[kc * 32 * 256 + idx];
        __syncthreads();
#pragma unroll 4
        for (int k = 0; k < 32; k++) {
            float w0 = Wsm[k * 256 + col];
            float w1 = Wsm[k * 256 + col + 64];
            float w2 = Wsm[k * 256 + col + 128];
            float w3 = Wsm[k * 256 + col + 192];
            int kk = kc * 32 + k;
#pragma unroll
            for (int rr = 0; rr < 8; rr++) {
                float l = Lsm[(rgrp * 8 + rr) * 64 + kk];
                acc[0][rr] += l * w0;
                acc[1][rr] += l * w1;
                acc[2][rr] += l * w2;
                acc[3][rr] += l * w3;
            }
        }
    }
#pragma unroll
    for (int rr = 0; rr < 8; rr++) {
        size_t row = rowbase + rgrp * 8 + rr;
        float* o = &g_P1[row * OUTC];
        o[col] = acc[0][rr];
        o[col + 64] = acc[1][rr];
        o[col + 128] = acc[2][rr];
        o[col + 192] = acc[3][rr];
    }
}

// Final: out[i] = P1[x_u] + P2b[t_u] + (sum_e P3[u_e]) / count   (0 for padded rows)
__global__ void k_final(float* __restrict__ out) {
    u32 K = g_numrows;
    int c = threadIdx.x;
#pragma unroll
    for (int r = 0; r < 4; r++) {
        int i = blockIdx.x * 4 + r;
        float v = 0.f;
        if (i < (int)K) {
            u32 key = g_key[i];
            u32 xu = key / NTIMES;
            u32 tu = key - xu * NTIMES;
            u32 cnt = g_count[i];
            u32 end = g_cursor[i];     // advanced to offset+count by scatter
            u32 start = end - cnt;
            float acc = 0.f;
            for (u32 e = start; e < end; e++) {
                u32 uu = g_evtu[e];
                acc += g_P3[uu * OUTC + c];
            }
            v = g_P1[(size_t)xu * OUTC + c] + g_P2b[tu * OUTC + c] +
                acc * (1.0f / (float)cnt);
        }
        out[(size_t)i * OUTC + c] = v;
    }
}

// ---------------- launch ----------------
extern "C" void kernel_launch(void* const* d_in, const int* in_sizes, int n_in,
                              void* d_out, int out_size) {
    const int* x = (const int*)d_in[0];
    const int* t = (const int*)d_in[1];
    const int* u = (const int*)d_in[2];
    const float* loc_table = (const float*)d_in[3];
    const float* time_table = (const float*)d_in[4];
    const float* user_table = (const float*)d_in[5];
    const float* W = (const float*)d_in[6];
    const float* b = (const float*)d_in[7];
    float* out = (float*)d_out;

    k_zero<<<4096, 256>>>();
    k_hist<<<(NEVT + 255) / 256, 256>>>(x, t);
    k_s1<<<NSBLK, SCAN_T>>>();
    k_s2<<<1, 1024>>>();
    k_s3<<<NSBLK, SCAN_T>>>();
    k_scatter<<<(NEVT + 255) / 256, 256>>>(x, t, u);
    k_p23<<<NTIMES, 256>>>(time_table, user_table, W, b);
    k_p1<<<NLOCS / 32, 256>>>(loc_table, W);
    k_final<<<NEVT / 4, 256>>>(out);
}

// round 2
// speedup vs baseline: 1.0481x; 1.0481x over previous
#include <cuda_runtime.h>

#define NEVT    400000
#define NLOCS   100000
#define NTIMES  168
#define NKEYS   (NLOCS * NTIMES)          /* 16,800,000 */
#define NWORDS  (NKEYS / 4)               /* 4,200,000 u32 words of 4 u8 counters */
#define OUTC    256
#define SCAN_T  256
#define WPB     4096                      /* counter words per scan block */
#define NSBLK   ((NWORDS + WPB - 1) / WPB)/* 1026 */
#define HB      ((NEVT + 255) / 256)      /* 1563 hist/scatter blocks */
#define NTILES  (NLOCS / 32)              /* 3125 P1 tiles */
#define T_K2    782
#define T_K3    781
#define T_K5    781
#define T_K6    781

typedef unsigned int u32;
typedef unsigned long long u64;

// ---------------- scratch ----------------
__device__ u32 g_cntw[NWORDS];        // packed u8 histogram (4 counters / word)
__device__ u32 g_rowid[NKEYS];        // key -> unique-row id (sparse)
__device__ u64 g_bsums[NSBLK];        // packed (flags<<32 | counts) block sums
__device__ u32 g_numrows;
__device__ u32 g_key[NEVT];
__device__ u32 g_count[NEVT];
__device__ u32 g_cursor[NEVT];
__device__ u32 g_evtu[NEVT];
__device__ float g_P1[(size_t)NLOCS * OUTC];
__device__ float g_P2b[NTIMES * OUTC];
__device__ float g_P3[NTIMES * OUTC];

// ---------------- helpers ----------------
__device__ __forceinline__ u64 ffma2(u64 a, u64 b, u64 c) {
    u64 d;
    asm("fma.rn.f32x2 %0, %1, %2, %3;" : "=l"(d) : "l"(a), "l"(b), "l"(c));
    return d;
}
__device__ __forceinline__ u64 pack2(float lo, float hi) {
    u64 r;
    asm("mov.b64 %0, {%1, %2};" : "=l"(r) : "f"(lo), "f"(hi));
    return r;
}
__device__ __forceinline__ void unpack2(u64 v, float& lo, float& hi) {
    asm("mov.b64 {%0, %1}, %2;" : "=f"(lo), "=f"(hi) : "l"(v));
}

template <int NT>
__device__ __forceinline__ u64 block_incl_scan(u64 v, u64* sm) {
    int tid = threadIdx.x;
    int lane = tid & 31, wid = tid >> 5;
    u64 x = v;
#pragma unroll
    for (int d = 1; d < 32; d <<= 1) {
        u64 y = __shfl_up_sync(0xffffffffu, x, d);
        if (lane >= d) x += y;
    }
    if (lane == 31) sm[wid] = x;
    __syncthreads();
    if (wid == 0) {
        u64 w = (lane < (NT / 32)) ? sm[lane] : 0ull;
#pragma unroll
        for (int d = 1; d < 32; d <<= 1) {
            u64 y = __shfl_up_sync(0xffffffffu, w, d);
            if (lane >= d) w += y;
        }
        if (lane < (NT / 32)) sm[lane] = w;
    }
    __syncthreads();
    u64 base = wid ? sm[wid - 1] : 0ull;
    u64 r = x + base;
    __syncthreads();
    return r;
}

// ---- P1 tile: 32 loc rows x 256 cols, K=64, FFMA2 register-tiled ----
__device__ __forceinline__ void p1_tile(int tile, const float* __restrict__ loc_table,
                                        const float* __restrict__ W) {
    __shared__ __align__(16) float Wsm[32 * 256];
    __shared__ __align__(16) float Lsm[32 * 64];
    int tid = threadIdx.x;
    int rowbase = tile * 32;
    for (int idx = tid; idx < 32 * 64; idx += 256)
        Lsm[idx] = loc_table[(size_t)rowbase * 64 + idx];
    int cp = tid & 31;     // col pair within 64-col group: cols 2cp, 2cp+1
    int w = tid >> 5;      // warp -> rows w*4 .. w*4+3
    u64 acc[4][4];
#pragma unroll
    for (int g = 0; g < 4; g++)
#pragma unroll
        for (int r = 0; r < 4; r++) acc[g][r] = 0ull;

    for (int kc = 0; kc < 2; kc++) {
        __syncthreads();
        for (int idx = tid; idx < 32 * 256; idx += 256)
            Wsm[idx] = W[kc * 32 * 256 + idx];
        __syncthreads();
#pragma unroll 4
        for (int k = 0; k < 32; k++) {
            const u64* wrow = reinterpret_cast<const u64*>(&Wsm[k * 256]);
            u64 wv0 = wrow[cp];
            u64 wv1 = wrow[32 + cp];
            u64 wv2 = wrow[64 + cp];
            u64 wv3 = wrow[96 + cp];
            int kk = kc * 32 + k;
#pragma unroll
            for (int r = 0; r < 4; r++) {
                float l = Lsm[(w * 4 + r) * 64 + kk];
                u64 ll = pack2(l, l);
                acc[0][r] = ffma2(ll, wv0, acc[0][r]);
                acc[1][r] = ffma2(ll, wv1, acc[1][r]);
                acc[2][r] = ffma2(ll, wv2, acc[2][r]);
                acc[3][r] = ffma2(ll, wv3, acc[3][r]);
            }
        }
    }
#pragma unroll
    for (int r = 0; r < 4; r++) {
        size_t row = rowbase + w * 4 + r;
        float2* o = reinterpret_cast<float2*>(&g_P1[row * OUTC]);
#pragma unroll
        for (int g = 0; g < 4; g++) {
            float lo, hi;
            unpack2(acc[g][r], lo, hi);
            o[g * 32 + cp] = make_float2(lo, hi);
        }
    }
}

// ---------------- stage bodies ----------------
__device__ __forceinline__ void hist_body(int b, const int* __restrict__ x,
                                          const int* __restrict__ t) {
    int j = b * 256 + threadIdx.x;
    if (j < NEVT) {
        u32 key = (u32)x[j] * NTIMES + (u32)t[j];
        atomicAdd(&g_cntw[key >> 2], 1u << ((key & 3) * 8));
    }
}

__device__ __forceinline__ void s1_body(int b) {
    int tid = threadIdx.x;
    size_t base = (size_t)b * WPB;
    u32 fs = 0, cs = 0;
#pragma unroll
    for (int j = 0; j < WPB / SCAN_T; j++) {
        size_t idx = base + j * SCAN_T + tid;
        u32 wv = (idx < NWORDS) ? g_cntw[idx] : 0u;
        cs = __dp4a(wv, 0x01010101u, cs);
        fs += __popc(__vcmpne4(wv, 0u) & 0x01010101u);
    }
    u64 v = ((u64)fs << 32) | cs;
    __shared__ u64 sm[SCAN_T / 32];
    int lane = tid & 31, wid = tid >> 5;
#pragma unroll
    for (int d = 16; d; d >>= 1) v += __shfl_down_sync(0xffffffffu, v, d);
    if (lane == 0) sm[wid] = v;
    __syncthreads();
    if (tid == 0) {
        u64 s = 0;
        for (int i = 0; i < SCAN_T / 32; i++) s += sm[i];
        g_bsums[b] = s;
    }
}

__device__ __forceinline__ void s3_body(int b) {
    __shared__ u32 s_w[WPB];
    __shared__ u64 sm2[SCAN_T / 32];
    int tid = threadIdx.x;
    size_t base = (size_t)b * WPB;
    for (int j = 0; j < WPB / SCAN_T; j++) {
        size_t idx = base + j * SCAN_T + tid;
        s_w[j * SCAN_T + tid] = (idx < NWORDS) ? g_cntw[idx] : 0u;
    }
    __syncthreads();
    int w0 = tid * (WPB / SCAN_T);    // 16 contiguous words per thread
    u32 fs = 0, cs = 0;
#pragma unroll
    for (int j = 0; j < WPB / SCAN_T; j++) {
        u32 wv = s_w[w0 + j];
        cs = __dp4a(wv, 0x01010101u, cs);
        fs += __popc(__vcmpne4(wv, 0u) & 0x01010101u);
    }
    u64 mine = ((u64)fs << 32) | cs;
    u64 incl = block_incl_scan<SCAN_T>(mine, sm2);
    u64 excl = incl - mine;
    u64 bbase = g_bsums[b];
    u32 frun = (u32)((excl >> 32) + (bbase >> 32));
    u32 crun = (u32)(excl & 0xffffffffull) + (u32)(bbase & 0xffffffffull);
#pragma unroll
    for (int j = 0; j < WPB / SCAN_T; j++) {
        u32 wv = s_w[w0 + j];
        if (!wv) continue;
#pragma unroll
        for (int lane = 0; lane < 4; lane++) {
            u32 c = (wv >> (lane * 8)) & 0xffu;
            if (c) {
                u32 key = (u32)((base + w0 + j) * 4 + lane);
                g_key[frun] = key;
                g_count[frun] = c;
                g_cursor[frun] = crun;
                g_rowid[key] = frun;
                frun++;
                crun += c;
            }
        }
    }
}

__device__ __forceinline__ void scatter_body(int b, const int* __restrict__ x,
                                             const int* __restrict__ t,
                                             const int* __restrict__ u) {
    int j = b * 256 + threadIdx.x;
    if (j < NEVT) {
        u32 key = (u32)x[j] * NTIMES + (u32)t[j];
        u32 row = g_rowid[key];
        u32 pos = atomicAdd(&g_cursor[row], 1u);
        g_evtu[pos] = (u32)u[j];
    }
}

// ---------------- kernels ----------------
__global__ void k1_zero_p23(const float* __restrict__ time_table,
                            const float* __restrict__ user_table,
                            const float* __restrict__ W, const float* __restrict__ b) {
    if (blockIdx.x < NTIMES) {
        int r = blockIdx.x;
        int c = threadIdx.x;
        float a2 = b[c];
#pragma unroll 8
        for (int k = 0; k < 32; k++)
            a2 += time_table[r * 32 + k] * W[(64 + k) * OUTC + c];
        g_P2b[r * OUTC + c] = a2;
        float a3 = 0.f;
#pragma unroll 8
        for (int k = 0; k < 64; k++)
            a3 += user_table[r * 64 + k] * W[(96 + k) * OUTC + c];
        g_P3[r * OUTC + c] = a3;
    } else {
        int zb = blockIdx.x - NTIMES;
        uint4 z = make_uint4(0, 0, 0, 0);
        uint4* p = reinterpret_cast<uint4*>(g_cntw);
        for (size_t idx = (size_t)zb * 256 + threadIdx.x; idx < NWORDS / 4;
             idx += (size_t)1024 * 256)
            p[idx] = z;
    }
}

__global__ void __launch_bounds__(256) k2_hist_p1(const int* __restrict__ x,
                                                  const int* __restrict__ t,
                                                  const float* __restrict__ loc,
                                                  const float* __restrict__ W) {
    if (blockIdx.x < HB) hist_body(blockIdx.x, x, t);
    else p1_tile(blockIdx.x - HB, loc, W);
}

__global__ void __launch_bounds__(256) k3_s1_p1(const float* __restrict__ loc,
                                                const float* __restrict__ W) {
    if (blockIdx.x < NSBLK) s1_body(blockIdx.x);
    else p1_tile(blockIdx.x - NSBLK + T_K2, loc, W);
}

__global__ void k4_s2() {
    __shared__ u64 sm[32];
    __shared__ u64 s_carry;
    __shared__ u64 s_total;
    int tid = threadIdx.x;
    if (tid == 0) s_carry = 0;
    __syncthreads();
    for (int base = 0; base < NSBLK; base += 1024) {
        int i = base + tid;
        u64 v = (i < NSBLK) ? g_bsums[i] : 0ull;
        u64 incl = block_incl_scan<1024>(v, sm);
        if (tid == 1023) s_total = incl;
        __syncthreads();
        u64 carry = s_carry;
        if (i < NSBLK) g_bsums[i] = carry + incl - v;
        __syncthreads();
        if (tid == 0) s_carry = carry + s_total;
        __syncthreads();
    }
    if (tid == 0) g_numrows = (u32)(s_carry >> 32);
}

__global__ void __launch_bounds__(256) k5_s3_p1(const float* __restrict__ loc,
                                                const float* __restrict__ W) {
    if (blockIdx.x < NSBLK) s3_body(blockIdx.x);
    else p1_tile(blockIdx.x - NSBLK + T_K2 + T_K3, loc, W);
}

__global__ void __launch_bounds__(256) k6_scatter_p1(const int* __restrict__ x,
                                                     const int* __restrict__ t,
                                                     const int* __restrict__ u,
                                                     const float* __restrict__ loc,
                                                     const float* __restrict__ W) {
    if (blockIdx.x < HB) scatter_body(blockIdx.x, x, t, u);
    else p1_tile(blockIdx.x - HB + T_K2 + T_K3 + T_K5, loc, W);
}

__global__ void __launch_bounds__(512) k7_final(float* __restrict__ out) {
    u32 K = g_numrows;
    int tid = threadIdx.x;
    int r = tid >> 7;          // 4 rows per block
    int c2 = tid & 127;        // float2 column
    int i = blockIdx.x * 4 + r;
    float2 v = make_float2(0.f, 0.f);
    if (i < (int)K) {
        u32 key = g_key[i];
        u32 xu = key / NTIMES;
        u32 tu = key - xu * NTIMES;
        u32 cnt = g_count[i];
        u32 end = g_cursor[i];
        u32 start = end - cnt;
        const float2* P3f = reinterpret_cast<const float2*>(g_P3);
        float2 a = make_float2(0.f, 0.f);
        for (u32 e = start; e < end; e++) {
            u32 uu = g_evtu[e];
            float2 p = P3f[uu * 128 + c2];
            a.x += p.x;
            a.y += p.y;
        }
        float inv = 1.0f / (float)cnt;
        float2 p1v = reinterpret_cast<const float2*>(g_P1)[(size_t)xu * 128 + c2];
        float2 p2v = reinterpret_cast<const float2*>(g_P2b)[tu * 128 + c2];
        v.x = p1v.x + p2v.x + a.x * inv;
        v.y = p1v.y + p2v.y + a.y * inv;
    }
    reinterpret_cast<float2*>(out)[(size_t)i * 128 + c2] = v;
}

// ---------------- launch ----------------
extern "C" void kernel_launch(void* const* d_in, const int* in_sizes, int n_in,
                              void* d_out, int out_size) {
    const int* x = (const int*)d_in[0];
    const int* t = (const int*)d_in[1];
    const int* u = (const int*)d_in[2];
    const float* loc_table = (const float*)d_in[3];
    const float* time_table = (const float*)d_in[4];
    const float* user_table = (const float*)d_in[5];
    const float* W = (const float*)d_in[6];
    const float* b = (const float*)d_in[7];
    float* out = (float*)d_out;

    k1_zero_p23<<<NTIMES + 1024, 256>>>(time_table, user_table, W, b);
    k2_hist_p1<<<HB + T_K2, 256>>>(x, t, loc_table, W);
    k3_s1_p1<<<NSBLK + T_K3, 256>>>(loc_table, W);
    k4_s2<<<1, 1024>>>();
    k5_s3_p1<<<NSBLK + T_K5, 256>>>(loc_table, W);
    k6_scatter_p1<<<HB + T_K6, 256>>>(x, t, u, loc_table, W);
    k7_final<<<NEVT / 4, 512>>>(out);
}

// round 3
// speedup vs baseline: 1.4915x; 1.4230x over previous
#include <cuda_runtime.h>

#define NEVT    400000
#define NLOCS   100000
#define NTIMES  168
#define NKEYS   (NLOCS * NTIMES)          /* 16,800,000 */
#define NWORDS  (NKEYS / 4)               /* 4,200,000 packed counter words */
#define OUTC    256
#define SCAN_T  256
#define WPB     4096                      /* counter words per scan block */
#define NSBLK   ((NWORDS + WPB - 1) / WPB)/* 1026 */
#define HB      ((NEVT + 255) / 256)      /* 1563 */
#define NTILES  (NLOCS / 32)              /* 3125 P1 tiles */
#define T1      1042
#define T2      1042
#define T3      1041

typedef unsigned int u32;
typedef unsigned long long u64;

// ---------------- scratch ----------------
__device__ u32 g_cntw[NWORDS];        // packed u8 histogram (zeroed by cleanup each replay)
__device__ u32 g_rowid[NKEYS];        // key -> unique-row id (sparse writes only)
__device__ u64 g_state[NSBLK];        // decoupled-lookback state
__device__ u32 g_numrows;
__device__ u32 g_key[NEVT];
__device__ u32 g_count[NEVT];
__device__ u32 g_cursor[NEVT];
__device__ u32 g_evtu[NEVT];
__device__ __align__(16) float g_P1[(size_t)NLOCS * OUTC];
__device__ __align__(16) float g_P2b[NTIMES * OUTC];
__device__ __align__(16) float g_P3[NTIMES * OUTC];

// ---------------- helpers ----------------
__device__ __forceinline__ u64 ffma2(u64 a, u64 b, u64 c) {
    u64 d;
    asm("fma.rn.f32x2 %0, %1, %2, %3;" : "=l"(d) : "l"(a), "l"(b), "l"(c));
    return d;
}
__device__ __forceinline__ u64 pack2(float lo, float hi) {
    u64 r;
    asm("mov.b64 %0, {%1, %2};" : "=l"(r) : "f"(lo), "f"(hi));
    return r;
}
__device__ __forceinline__ void unpack2(u64 v, float& lo, float& hi) {
    asm("mov.b64 {%0, %1}, %2;" : "=f"(lo), "=f"(hi) : "l"(v));
}

template <int NT>
__device__ __forceinline__ u64 block_incl_scan(u64 v, u64* sm) {
    int tid = threadIdx.x;
    int lane = tid & 31, wid = tid >> 5;
    u64 x = v;
#pragma unroll
    for (int d = 1; d < 32; d <<= 1) {
        u64 y = __shfl_up_sync(0xffffffffu, x, d);
        if (lane >= d) x += y;
    }
    if (lane == 31) sm[wid] = x;
    __syncthreads();
    if (wid == 0) {
        u64 w = (lane < (NT / 32)) ? sm[lane] : 0ull;
#pragma unroll
        for (int d = 1; d < 32; d <<= 1) {
            u64 y = __shfl_up_sync(0xffffffffu, w, d);
            if (lane >= d) w += y;
        }
        if (lane < (NT / 32)) sm[lane] = w;
    }
    __syncthreads();
    u64 base = wid ? sm[wid - 1] : 0ull;
    u64 r = x + base;
    __syncthreads();
    return r;
}

// ---- P1 tile: 32 loc rows x 256 cols, K=64, FFMA2 ----
__device__ __forceinline__ void p1_tile(int tile, const float* __restrict__ loc_table,
                                        const float* __restrict__ W) {
    __shared__ __align__(16) float Wsm[32 * 256];
    __shared__ __align__(16) float Lsm[32 * 64];
    int tid = threadIdx.x;
    int rowbase = tile * 32;
    for (int idx = tid; idx < 32 * 64; idx += 256)
        Lsm[idx] = loc_table[(size_t)rowbase * 64 + idx];
    int cp = tid & 31;
    int w = tid >> 5;
    u64 acc[4][4];
#pragma unroll
    for (int g = 0; g < 4; g++)
#pragma unroll
        for (int r = 0; r < 4; r++) acc[g][r] = 0ull;

    for (int kc = 0; kc < 2; kc++) {
        __syncthreads();
        for (int idx = tid; idx < 32 * 256; idx += 256)
            Wsm[idx] = W[kc * 32 * 256 + idx];
        __syncthreads();
#pragma unroll 4
        for (int k = 0; k < 32; k++) {
            const u64* wrow = reinterpret_cast<const u64*>(&Wsm[k * 256]);
            u64 wv0 = wrow[cp];
            u64 wv1 = wrow[32 + cp];
            u64 wv2 = wrow[64 + cp];
            u64 wv3 = wrow[96 + cp];
            int kk = kc * 32 + k;
#pragma unroll
            for (int r = 0; r < 4; r++) {
                float l = Lsm[(w * 4 + r) * 64 + kk];
                u64 ll = pack2(l, l);
                acc[0][r] = ffma2(ll, wv0, acc[0][r]);
                acc[1][r] = ffma2(ll, wv1, acc[1][r]);
                acc[2][r] = ffma2(ll, wv2, acc[2][r]);
                acc[3][r] = ffma2(ll, wv3, acc[3][r]);
            }
        }
    }
#pragma unroll
    for (int r = 0; r < 4; r++) {
        size_t row = rowbase + w * 4 + r;
        float2* o = reinterpret_cast<float2*>(&g_P1[row * OUTC]);
#pragma unroll
        for (int g = 0; g < 4; g++) {
            float lo, hi;
            unpack2(acc[g][r], lo, hi);
            o[g * 32 + cp] = make_float2(lo, hi);
        }
    }
}

// ---------------- stage bodies ----------------
__device__ __forceinline__ void hist_body(int b, const int* __restrict__ x,
                                          const int* __restrict__ t) {
    int j = b * 256 + threadIdx.x;
    if (j < NEVT) {
        u32 key = (u32)__ldg(&x[j]) * NTIMES + (u32)__ldg(&t[j]);
        atomicAdd(&g_cntw[key >> 2], 1u << ((key & 3) * 8));
    }
}

__device__ __forceinline__ void p23_body(int r, const float* __restrict__ time_table,
                                         const float* __restrict__ user_table,
                                         const float* __restrict__ W,
                                         const float* __restrict__ b) {
    int c = threadIdx.x;
    float a2 = b[c];
#pragma unroll 8
    for (int k = 0; k < 32; k++)
        a2 += time_table[r * 32 + k] * W[(64 + k) * OUTC + c];
    g_P2b[r * OUTC + c] = a2;
    float a3 = 0.f;
#pragma unroll 8
    for (int k = 0; k < 64; k++)
        a3 += user_table[r * 64 + k] * W[(96 + k) * OUTC + c];
    g_P3[r * OUTC + c] = a3;
}

// single-pass scan + emit with decoupled lookback
__device__ __forceinline__ void scan_emit_body(int b) {
    __shared__ u32 s_w[WPB];
    __shared__ u64 sm2[SCAN_T / 32];
    __shared__ u64 s_bcast;
    int tid = threadIdx.x;
    size_t base = (size_t)b * WPB;
    for (int j = 0; j < WPB / SCAN_T; j++) {
        size_t idx = base + j * SCAN_T + tid;
        s_w[j * SCAN_T + tid] = (idx < NWORDS) ? g_cntw[idx] : 0u;
    }
    __syncthreads();
    int w0 = tid * (WPB / SCAN_T);
    u32 fs = 0, cs = 0;
#pragma unroll
    for (int j = 0; j < WPB / SCAN_T; j++) {
        u32 wv = s_w[w0 + j];
        cs = __dp4a(wv, 0x01010101u, cs);
        fs += __popc(__vcmpne4(wv, 0u) & 0x01010101u);
    }
    // pack: counts [0:24), flags [24:48)   (totals < 2^24 -> no cross-field carry)
    u64 mine = ((u64)fs << 24) | cs;
    u64 incl = block_incl_scan<SCAN_T>(mine, sm2);
    u64 excl = incl - mine;
    if (tid == SCAN_T - 1) s_bcast = incl;   // block total
    __syncthreads();
    if (tid == 0) {
        u64 total = s_bcast;
        u64 prefix = 0;
        if (b == 0) {
            atomicExch((unsigned long long*)&g_state[0], (2ull << 62) | total);
        } else {
            atomicExch((unsigned long long*)&g_state[b], (1ull << 62) | total);
            int i = b - 1;
            while (true) {
                u64 v = atomicAdd((unsigned long long*)&g_state[i], 0ull);
                u64 st = v >> 62;
                if (st == 0) { __nanosleep(40); continue; }
                prefix += v & 0x3FFFFFFFFFFFFFFFull;
                if (st == 2) break;
                i--;
            }
            atomicExch((unsigned long long*)&g_state[b], (2ull << 62) | (prefix + total));
        }
        if (b == NSBLK - 1)
            g_numrows = (u32)(((prefix + total) >> 24) & 0xFFFFFFu);
        s_bcast = prefix;
    }
    __syncthreads();
    u64 run = s_bcast + excl;
    u32 frun = (u32)((run >> 24) & 0xFFFFFFu);
    u32 crun = (u32)(run & 0xFFFFFFu);
#pragma unroll
    for (int j = 0; j < WPB / SCAN_T; j++) {
        u32 wv = s_w[w0 + j];
        if (!wv) continue;
#pragma unroll
        for (int lane = 0; lane < 4; lane++) {
            u32 c = (wv >> (lane * 8)) & 0xffu;
            if (c) {
                u32 key = (u32)((base + w0 + j) * 4 + lane);
                g_key[frun] = key;
                g_count[frun] = c;
                g_cursor[frun] = crun;
                g_rowid[key] = frun;
                frun++;
                crun += c;
            }
        }
    }
}

__device__ __forceinline__ void scatter_body(int b, const int* __restrict__ x,
                                             const int* __restrict__ t,
                                             const int* __restrict__ u) {
    int j = b * 256 + threadIdx.x;
    if (j < NEVT) {
        u32 key = (u32)__ldg(&x[j]) * NTIMES + (u32)__ldg(&t[j]);
        u32 row = g_rowid[key];
        u32 pos = atomicAdd(&g_cursor[row], 1u);
        g_evtu[pos] = (u32)__ldg(&u[j]);
    }
}

// ---------------- kernels (k_final MUST be the 4th launch for ncu capture) ----------------
__global__ void __launch_bounds__(256) k1_p1_p23_hist(const int* __restrict__ x,
                                                      const int* __restrict__ t,
                                                      const float* __restrict__ loc,
                                                      const float* __restrict__ time_table,
                                                      const float* __restrict__ user_table,
                                                      const float* __restrict__ W,
                                                      const float* __restrict__ b) {
    int bid = blockIdx.x;
    if (bid < T1) p1_tile(bid, loc, W);
    else if (bid < T1 + NTIMES) p23_body(bid - T1, time_table, user_table, W, b);
    else hist_body(bid - T1 - NTIMES, x, t);
}

__global__ void __launch_bounds__(256) k2_scan_p1(const float* __restrict__ loc,
                                                  const float* __restrict__ W) {
    int bid = blockIdx.x;
    if (bid < NSBLK) scan_emit_body(bid);
    else p1_tile(bid - NSBLK + T1, loc, W);
}

__global__ void __launch_bounds__(256) k3_p1_scatter(const int* __restrict__ x,
                                                     const int* __restrict__ t,
                                                     const int* __restrict__ u,
                                                     const float* __restrict__ loc,
                                                     const float* __restrict__ W) {
    int bid = blockIdx.x;
    if (bid < T3) p1_tile(bid + T1 + T2, loc, W);
    else scatter_body(bid - T3, x, t, u);
}

__global__ void __launch_bounds__(512) k4_final(float* __restrict__ out) {
    u32 K = g_numrows;
    int tid = threadIdx.x;
    int r = tid >> 6;          // 8 rows per block
    int c4 = tid & 63;         // float4 column
    int i = blockIdx.x * 8 + r;
    float4 v = make_float4(0.f, 0.f, 0.f, 0.f);
    if (i < (int)K) {
        u32 key = g_key[i];
        u32 xu = key / NTIMES;
        u32 tu = key - xu * NTIMES;
        u32 cnt = g_count[i];
        u32 end = g_cursor[i];
        u32 start = end - cnt;
        const float4* P3f = reinterpret_cast<const float4*>(g_P3);
        float4 a = make_float4(0.f, 0.f, 0.f, 0.f);
        for (u32 e = start; e < end; e++) {
            u32 uu = g_evtu[e];
            float4 p = P3f[uu * 64 + c4];
            a.x += p.x; a.y += p.y; a.z += p.z; a.w += p.w;
        }
        float inv = 1.0f / (float)cnt;
        float4 p1v = reinterpret_cast<const float4*>(g_P1)[(size_t)xu * 64 + c4];
        float4 p2v = reinterpret_cast<const float4*>(g_P2b)[tu * 64 + c4];
        v.x = p1v.x + p2v.x + a.x * inv;
        v.y = p1v.y + p2v.y + a.y * inv;
        v.z = p1v.z + p2v.z + a.z * inv;
        v.w = p1v.w + p2v.w + a.w * inv;
    }
    __stcs(&reinterpret_cast<float4*>(out)[(size_t)i * 64 + c4], v);
}

// restore pre-replay state: zero only touched counter words + lookback state
__global__ void __launch_bounds__(256) k5_cleanup(const int* __restrict__ x,
                                                  const int* __restrict__ t) {
    int j = blockIdx.x * 256 + threadIdx.x;
    if (j < NEVT) {
        u32 key = (u32)__ldg(&x[j]) * NTIMES + (u32)__ldg(&t[j]);
        g_cntw[key >> 2] = 0u;
    }
    if (blockIdx.x == 0) {
        for (int i = threadIdx.x; i < NSBLK; i += 256) g_state[i] = 0ull;
    }
}

// ---------------- launch ----------------
extern "C" void kernel_launch(void* const* d_in, const int* in_sizes, int n_in,
                              void* d_out, int out_size) {
    const int* x = (const int*)d_in[0];
    const int* t = (const int*)d_in[1];
    const int* u = (const int*)d_in[2];
    const float* loc_table = (const float*)d_in[3];
    const float* time_table = (const float*)d_in[4];
    const float* user_table = (const float*)d_in[5];
    const float* W = (const float*)d_in[6];
    const float* b = (const float*)d_in[7];
    float* out = (float*)d_out;

    k1_p1_p23_hist<<<T1 + NTIMES + HB, 256>>>(x, t, loc_table, time_table,
                                              user_table, W, b);
    k2_scan_p1<<<NSBLK + T2, 256>>>(loc_table, W);
    k3_p1_scatter<<<T3 + HB, 256>>>(x, t, u, loc_table, W);
    k4_final<<<NEVT / 8, 512>>>(out);
    k5_cleanup<<<HB, 256>>>(x, t);
}